// round 12
// baseline (speedup 1.0000x reference)
#include <cuda_runtime.h>
#include <cuda_bf16.h>
#include <cstdint>

#define Bn      4096
#define Dn      256
#define NEXP    4
#define NPAIR   6
#define TMm     64
#define TNn     128
#define KC      32
#define SPLITK  6
#define NLT     48                      // 6 pairs x 4 mt x 2 nt
#define APAD    72                      // A smem row stride (bf16)
#define BPAD    136                     // B smem row stride (bf16)
#define STG     4
#define NCHC    256                     // conv chunks per expert (16 rows each)
#define TILEF   (TMm * TNn)             // 8192 floats per logical tile
#define AOP     (KC * APAD)             // 2304 bf16
#define BOP     (KC * BPAD)             // 4352 bf16
#define STAGEE  (AOP + BOP)             // 6656 bf16 per stage
#define DYN_SMEM (STG * STAGEE * 2)     // 53248 B

// -------- scratch ---------------------------------------------------------
__device__ float          g_partMean[NEXP * NCHC * Dn];
__device__ __nv_bfloat16  g_z[NEXP * Bn * Dn];
__device__ float          g_partC[(size_t)SPLITK * NLT * TILEF];   // 9.4MB
__device__ float          g_bsum[NLT];
__device__ unsigned       g_tileCnt[NLT];
__device__ unsigned       g_cnt;

__constant__ int c_pi[NPAIR] = {0, 0, 0, 1, 1, 2};
__constant__ int c_pj[NPAIR] = {1, 2, 3, 2, 3, 3};
__constant__ int c_kbase[SPLITK] = {0, 22, 44, 65, 86, 107};
__constant__ int c_kcnt[SPLITK]  = {22, 22, 21, 21, 21, 21};

// -------- kernel 1: fp32->bf16 convert + column partial sums --------------
__global__ __launch_bounds__(256, 4)
void conv_colsum_kernel(const float* __restrict__ e0,
                        const float* __restrict__ e1,
                        const float* __restrict__ e2,
                        const float* __restrict__ e3) {
    if (blockIdx.x == 0 && blockIdx.y == 0) {
        if (threadIdx.x == 0) g_cnt = 0;
        if (threadIdx.x < NLT) g_tileCnt[threadIdx.x] = 0;
    }
    int e  = blockIdx.y;
    int ch = blockIdx.x;
    const float* E = (e == 0) ? e0 : (e == 1) ? e1 : (e == 2) ? e2 : e3;
    int t  = threadIdx.x;
    int c4 = t & 63;
    int rq = t >> 6;

    const float4* src = (const float4*)E + (size_t)(ch * 16) * 64 + c4;
    uint2* dst = (uint2*)g_z + ((size_t)e * Bn + ch * 16) * 64 + c4;

    float4 v[4];
#pragma unroll
    for (int u = 0; u < 4; u++) v[u] = src[(size_t)(rq + u * 4) * 64];

    float4 s = make_float4(0.f, 0.f, 0.f, 0.f);
#pragma unroll
    for (int u = 0; u < 4; u++) {
        s.x += v[u].x; s.y += v[u].y; s.z += v[u].z; s.w += v[u].w;
        __nv_bfloat162 lo = __floats2bfloat162_rn(v[u].x, v[u].y);
        __nv_bfloat162 hi = __floats2bfloat162_rn(v[u].z, v[u].w);
        uint2 pk;
        pk.x = *(unsigned*)&lo; pk.y = *(unsigned*)&hi;
        dst[(size_t)(rq + u * 4) * 64] = pk;
    }
    __shared__ float4 red[4][64];
    red[rq][c4] = s;
    __syncthreads();
    if (t < 64) {
        float4 a = red[0][t], b = red[1][t], c = red[2][t], d = red[3][t];
        ((float4*)&g_partMean[(e * NCHC + ch) * Dn])[t] =
            make_float4(a.x + b.x + c.x + d.x, a.y + b.y + c.y + d.y,
                        a.z + b.z + c.z + d.z, a.w + b.w + c.w + d.w);
    }
}

// -------- HMMA helpers ----------------------------------------------------
__device__ __forceinline__ void cpa16(const void* smem, const void* g) {
    unsigned s = (unsigned)__cvta_generic_to_shared(smem);
    asm volatile("cp.async.cg.shared.global [%0], [%1], 16;\n" :: "r"(s), "l"(g));
}
__device__ __forceinline__ void cp_commit() {
    asm volatile("cp.async.commit_group;\n");
}
__device__ __forceinline__ void cp_wait2() {
    asm volatile("cp.async.wait_group 2;\n");
}
__device__ __forceinline__ void cp_wait0() {
    asm volatile("cp.async.wait_group 0;\n");
}
__device__ __forceinline__ void ldm_x4t(unsigned* r, const void* p) {
    unsigned a = (unsigned)__cvta_generic_to_shared(p);
    asm volatile("ldmatrix.sync.aligned.m8n8.x4.trans.shared.b16 "
                 "{%0,%1,%2,%3}, [%4];"
                 : "=r"(r[0]), "=r"(r[1]), "=r"(r[2]), "=r"(r[3]) : "r"(a));
}
__device__ __forceinline__ void mma16816(float* c, const unsigned* a,
                                         unsigned b0, unsigned b1) {
    asm volatile("mma.sync.aligned.m16n8k16.row.col.f32.bf16.bf16.f32 "
                 "{%0,%1,%2,%3},{%4,%5,%6,%7},{%8,%9},{%0,%1,%2,%3};"
                 : "+f"(c[0]), "+f"(c[1]), "+f"(c[2]), "+f"(c[3])
                 : "r"(a[0]), "r"(a[1]), "r"(a[2]), "r"(a[3]), "r"(b0), "r"(b1));
}

// -------- kernel 2: 64x128 HMMA GEMM, 128 threads, split-K=6 --------------
__global__ __launch_bounds__(128, 4)
void gemm_kernel(float* __restrict__ out) {
    extern __shared__ __align__(16) __nv_bfloat16 dsm[];  // [STG][A | B]
    __shared__ float tailv[TMm + TNn];    // 192
    __shared__ float sred[4];
    __shared__ float fr[64];
    __shared__ int s_do, s_last;

    int tile = blockIdx.x;                // 0..7: mt=tile>>1 (4), nt=tile&1 (2)
    int pair = blockIdx.y;
    int slab = blockIdx.z;
    int lt   = pair * 8 + tile;
    int tm   = (tile >> 1) * TMm;
    int tn   = (tile & 1) * TNn;
    int pi = c_pi[pair], pj = c_pj[pair];
    int kbase = c_kbase[slab], kcnt = c_kcnt[slab];
    const __nv_bfloat16* A = g_z + (size_t)pi * Bn * Dn + (size_t)kbase * KC * Dn + tm;
    const __nv_bfloat16* B = g_z + (size_t)pj * Bn * Dn + (size_t)kbase * KC * Dn + tn;

    int t    = threadIdx.x;               // 128 threads
    int lane = t & 31;
    int w    = t >> 5;                    // 0..3
    int wm   = (w >> 1) * 32;             // 2 warps in M
    int wn   = (w & 1) * 64;              // 2 warps in N

    int grp = lane >> 3, r = lane & 7;
    int aRow = ((grp & 2) ? 8 : 0) + r;
    int aCol = wm + ((grp & 1) ? 8 : 0);
    int bRow = ((grp & 1) ? 8 : 0) + r;
    int bOff = ((grp & 2) ? 8 : 0);

    float acc[2][8][4] = {};

    // loader: A = 256 granules (32 rows x 8 segs), B = 512 (32 rows x 16 segs)
    // 768 granules / 128 threads = 6 per thread, 12KB per chunk
    auto issue = [&](int c) {
        if (c < kcnt) {
            __nv_bfloat16* sA = dsm + (size_t)(c & 3) * STAGEE;
            __nv_bfloat16* sB = sA + AOP;
#pragma unroll
            for (int i = 0; i < 6; i++) {
                int g = i * 128 + t;
                if (g < 256) {
                    int row = g >> 3, seg = g & 7;
                    cpa16(&sA[row * APAD + seg * 8],
                          A + (size_t)(c * KC + row) * Dn + seg * 8);
                } else {
                    int gb = g - 256;
                    int row = gb >> 4, seg = gb & 15;
                    cpa16(&sB[row * BPAD + seg * 8],
                          B + (size_t)(c * KC + row) * Dn + seg * 8);
                }
            }
        }
        cp_commit();
    };

    issue(0); issue(1); issue(2);

    // slab 0 prologue: rank-1 tail values
    if (slab == 0) {
        if (t < TMm) {
            float s = 0.0f;
#pragma unroll 16
            for (int c = 0; c < NCHC; c++) s += g_partMean[(pi * NCHC + c) * Dn + tm + t];
            tailv[t] = -64.0f * (s * (1.0f / (float)Bn));
        }
        {
            float s = 0.0f;
#pragma unroll 16
            for (int c = 0; c < NCHC; c++) s += g_partMean[(pj * NCHC + c) * Dn + tn + t];
            tailv[TMm + t] = 64.0f * (s * (1.0f / (float)Bn));
        }
    }

    for (int c = 0; c < kcnt; ++c) {
        cp_wait2();
        __syncthreads();
        issue(c + 3);

        const __nv_bfloat16* sA = dsm + (size_t)(c & 3) * STAGEE;
        const __nv_bfloat16* sB = sA + AOP;
#pragma unroll
        for (int s = 0; s < 2; ++s) {
            int k0 = s * 16;
            unsigned A0[4], A1[4], Bf[4][4];
            ldm_x4t(A0, &sA[(k0 + aRow) * APAD + aCol]);
            ldm_x4t(A1, &sA[(k0 + aRow) * APAD + aCol + 16]);
#pragma unroll
            for (int j = 0; j < 4; j++)
                ldm_x4t(Bf[j], &sB[(k0 + bRow) * BPAD + wn + j * 16 + bOff]);
#pragma unroll
            for (int j = 0; j < 4; j++) {
                mma16816(acc[0][2 * j],     A0, Bf[j][0], Bf[j][1]);
                mma16816(acc[0][2 * j + 1], A0, Bf[j][2], Bf[j][3]);
                mma16816(acc[1][2 * j],     A1, Bf[j][0], Bf[j][1]);
                mma16816(acc[1][2 * j + 1], A1, Bf[j][2], Bf[j][3]);
            }
        }
    }

    // rank-1 tail as one k=16 mma (slab 0 only)
    if (slab == 0) {
        cp_wait0();
        __syncthreads();
        {
            __nv_bfloat16* sA = dsm;
            __nv_bfloat16* sB = dsm + AOP;
            // A tail tile: 16 rows x 8 segs = 128 granules (one pass)
            {
                int row = t >> 3, seg = t & 7;
                uint4 gA = make_uint4(0u, 0u, 0u, 0u);
                if (row == 0) {
                    unsigned* pa = (unsigned*)&gA;
#pragma unroll
                    for (int q = 0; q < 4; q++) {
                        __nv_bfloat162 va = __floats2bfloat162_rn(
                            tailv[seg * 8 + 2 * q], tailv[seg * 8 + 2 * q + 1]);
                        pa[q] = *(unsigned*)&va;
                    }
                }
                *(uint4*)&sA[row * APAD + seg * 8] = gA;
            }
            // B tail tile: 16 rows x 16 segs = 256 granules (two passes)
#pragma unroll
            for (int pz = 0; pz < 2; pz++) {
                int g = pz * 128 + t;
                int row = g >> 4, seg = g & 15;
                uint4 gB = make_uint4(0u, 0u, 0u, 0u);
                if (row == 0) {
                    unsigned* pb = (unsigned*)&gB;
#pragma unroll
                    for (int q = 0; q < 4; q++) {
                        __nv_bfloat162 vb = __floats2bfloat162_rn(
                            tailv[TMm + seg * 8 + 2 * q],
                            tailv[TMm + seg * 8 + 2 * q + 1]);
                        pb[q] = *(unsigned*)&vb;
                    }
                }
                *(uint4*)&sB[row * BPAD + seg * 8] = gB;
            }
        }
        __syncthreads();
        {
            const __nv_bfloat16* sA = dsm;
            const __nv_bfloat16* sB = dsm + AOP;
            unsigned A0[4], A1[4], Bf[4][4];
            ldm_x4t(A0, &sA[aRow * APAD + aCol]);
            ldm_x4t(A1, &sA[aRow * APAD + aCol + 16]);
#pragma unroll
            for (int j = 0; j < 4; j++)
                ldm_x4t(Bf[j], &sB[bRow * BPAD + wn + j * 16 + bOff]);
#pragma unroll
            for (int j = 0; j < 4; j++) {
                mma16816(acc[0][2 * j],     A0, Bf[j][0], Bf[j][1]);
                mma16816(acc[0][2 * j + 1], A0, Bf[j][2], Bf[j][3]);
                mma16816(acc[1][2 * j],     A1, Bf[j][0], Bf[j][1]);
                mma16816(acc[1][2 * j + 1], A1, Bf[j][2], Bf[j][3]);
            }
        }
    }

    // store partial fragments (layout-oblivious, same bijection all slabs)
    {
        float4* dst4 = (float4*)(g_partC + ((size_t)slab * NLT + lt) * TILEF);
#pragma unroll
        for (int mi = 0; mi < 2; mi++)
#pragma unroll
            for (int nj = 0; nj < 8; nj++)
                dst4[(mi * 8 + nj) * 128 + t] = make_float4(
                    acc[mi][nj][0], acc[mi][nj][1], acc[mi][nj][2], acc[mi][nj][3]);
    }

    // ---- per-logical-tile ticket: 6th slab-arrival combines + squares ----
    if (t == 0) {
        __threadfence();
        unsigned tk = atomicAdd(&g_tileCnt[lt], 1u);
        s_do = (tk == SPLITK - 1) ? 1 : 0;
    }
    __syncthreads();

    if (s_do) {
        __threadfence();
        float acc2 = 0.0f;
        for (int i4 = t; i4 < TILEF / 4; i4 += 128) {
            float vx = 0.f, vy = 0.f, vz = 0.f, vw = 0.f;
#pragma unroll
            for (int s2 = 0; s2 < SPLITK; s2++) {
                float4 v = ((const float4*)(g_partC +
                            ((size_t)s2 * NLT + lt) * TILEF))[i4];
                vx += v.x; vy += v.y; vz += v.z; vw += v.w;
            }
            acc2 += vx * vx + vy * vy + vz * vz + vw * vw;
        }
#pragma unroll
        for (int o = 16; o > 0; o >>= 1)
            acc2 += __shfl_xor_sync(0xffffffffu, acc2, o);
        if (lane == 0) sred[w] = acc2;
        __syncthreads();
        if (t == 0) {
            float tot = sred[0] + sred[1] + sred[2] + sred[3];
            g_bsum[lt] = tot;
            __threadfence();
            unsigned tk2 = atomicAdd(&g_cnt, 1u);
            s_last = (tk2 == NLT - 1) ? 1 : 0;
        }
        __syncthreads();

        if (s_last) {
            __threadfence();
            if (t < 64) fr[t] = (t < NLT) ? g_bsum[t] : 0.0f;
            __syncthreads();
            if (t == 0) {
                float tot = 0.0f;
#pragma unroll
                for (int i = 0; i < NLT; i++) tot += fr[i];
                const float denom = 4095.0f * 4095.0f;
                out[0] = 0.1f * (tot / denom) * (1.0f / (float)NPAIR);
            }
        }
    }
}

// -------- launch ----------------------------------------------------------
extern "C" void kernel_launch(void* const* d_in, const int* in_sizes, int n_in,
                              void* d_out, int out_size) {
    const float* e0 = (const float*)d_in[0];
    const float* e1 = (const float*)d_in[1];
    const float* e2 = (const float*)d_in[2];
    const float* e3 = (const float*)d_in[3];
    float* out = (float*)d_out;

    cudaFuncSetAttribute(gemm_kernel,
                         cudaFuncAttributeMaxDynamicSharedMemorySize, DYN_SMEM);

    conv_colsum_kernel<<<dim3(NCHC, NEXP), 256>>>(e0, e1, e2, e3);
    gemm_kernel<<<dim3(8, NPAIR, SPLITK), 128, DYN_SMEM>>>(out);
}

// round 13
// speedup vs baseline: 1.4486x; 1.4486x over previous
#include <cuda_runtime.h>
#include <cuda_bf16.h>
#include <cstdint>

#define Bn      4096
#define Dn      256
#define NEXP    4
#define NPAIR   6
#define TMm     128
#define TNn     64
#define KC      32
#define SPLITK  6
#define NLT     48                      // 6 pairs x 2 mt x 4 nt
#define ASPAD   136                     // A smem row stride (bf16, 128-wide tile)
#define BSPAD   72                      // B smem row stride (bf16, 64-wide tile)
#define STG     4
#define NCHC    128                     // conv chunks per expert (32 rows each)
#define TILEF   (TMm * TNn)             // 8192 floats per logical tile
#define AOP     (KC * ASPAD)            // 4352 bf16
#define BOP     (KC * BSPAD)            // 2304 bf16
#define STAGEE  (AOP + BOP)             // 6656 bf16 per stage
#define DYN_SMEM (STG * STAGEE * 2)     // 53248 B
#define CSTRIDE (NLT * TILEF)           // 393216 floats per slab
#define SQBLK   192

// -------- scratch ---------------------------------------------------------
__device__ float          g_partMean[NEXP * NCHC * Dn];
__device__ __nv_bfloat16  g_z[NEXP * Bn * Dn];
__device__ float          g_partC[(size_t)SPLITK * CSTRIDE];   // 9.4MB
__device__ float          g_bsum[SQBLK];
__device__ unsigned       g_cnt;

__constant__ int c_pi[NPAIR] = {0, 0, 0, 1, 1, 2};
__constant__ int c_pj[NPAIR] = {1, 2, 3, 2, 3, 3};
__constant__ int c_kbase[SPLITK] = {0, 22, 44, 65, 86, 107};
__constant__ int c_kcnt[SPLITK]  = {22, 22, 21, 21, 21, 21};

// -------- kernel 1: fp32->bf16 convert + column partial sums --------------
// grid (NCHC, NEXP) = 512 blocks, 256 threads; 32 rows x 256 cols each.
__global__ __launch_bounds__(256, 2)
void conv_colsum_kernel(const float* __restrict__ e0,
                        const float* __restrict__ e1,
                        const float* __restrict__ e2,
                        const float* __restrict__ e3) {
    if (blockIdx.x == 0 && blockIdx.y == 0 && threadIdx.x == 0) g_cnt = 0;
    int e  = blockIdx.y;
    int ch = blockIdx.x;
    const float* E = (e == 0) ? e0 : (e == 1) ? e1 : (e == 2) ? e2 : e3;
    int t  = threadIdx.x;
    int c4 = t & 63;
    int rq = t >> 6;

    const float4* src = (const float4*)E + (size_t)(ch * 32) * 64 + c4;
    uint2* dst = (uint2*)g_z + ((size_t)e * Bn + ch * 32) * 64 + c4;

    float4 v[8];
#pragma unroll
    for (int u = 0; u < 8; u++) v[u] = src[(size_t)(rq + u * 4) * 64];

    float4 s = make_float4(0.f, 0.f, 0.f, 0.f);
#pragma unroll
    for (int u = 0; u < 8; u++) {
        s.x += v[u].x; s.y += v[u].y; s.z += v[u].z; s.w += v[u].w;
        __nv_bfloat162 lo = __floats2bfloat162_rn(v[u].x, v[u].y);
        __nv_bfloat162 hi = __floats2bfloat162_rn(v[u].z, v[u].w);
        uint2 pk;
        pk.x = *(unsigned*)&lo; pk.y = *(unsigned*)&hi;
        dst[(size_t)(rq + u * 4) * 64] = pk;
    }
    __shared__ float4 red[4][64];
    red[rq][c4] = s;
    __syncthreads();
    if (t < 64) {
        float4 a = red[0][t], b = red[1][t], c = red[2][t], d = red[3][t];
        ((float4*)&g_partMean[(e * NCHC + ch) * Dn])[t] =
            make_float4(a.x + b.x + c.x + d.x, a.y + b.y + c.y + d.y,
                        a.z + b.z + c.z + d.z, a.w + b.w + c.w + d.w);
    }
}

// -------- HMMA helpers ----------------------------------------------------
__device__ __forceinline__ void cpa16(const void* smem, const void* g) {
    unsigned s = (unsigned)__cvta_generic_to_shared(smem);
    asm volatile("cp.async.cg.shared.global [%0], [%1], 16;\n" :: "r"(s), "l"(g));
}
__device__ __forceinline__ void cp_commit() {
    asm volatile("cp.async.commit_group;\n");
}
__device__ __forceinline__ void cp_wait2() {
    asm volatile("cp.async.wait_group 2;\n");
}
__device__ __forceinline__ void cp_wait0() {
    asm volatile("cp.async.wait_group 0;\n");
}
__device__ __forceinline__ void ldm_x4t(unsigned* r, const void* p) {
    unsigned a = (unsigned)__cvta_generic_to_shared(p);
    asm volatile("ldmatrix.sync.aligned.m8n8.x4.trans.shared.b16 "
                 "{%0,%1,%2,%3}, [%4];"
                 : "=r"(r[0]), "=r"(r[1]), "=r"(r[2]), "=r"(r[3]) : "r"(a));
}
__device__ __forceinline__ void mma16816(float* c, const unsigned* a,
                                         unsigned b0, unsigned b1) {
    asm volatile("mma.sync.aligned.m16n8k16.row.col.f32.bf16.bf16.f32 "
                 "{%0,%1,%2,%3},{%4,%5,%6,%7},{%8,%9},{%0,%1,%2,%3};"
                 : "+f"(c[0]), "+f"(c[1]), "+f"(c[2]), "+f"(c[3])
                 : "r"(a[0]), "r"(a[1]), "r"(a[2]), "r"(a[3]), "r"(b0), "r"(b1));
}

// -------- kernel 2: 128x64 HMMA GEMM, 256 threads, occ 2, split-K=6 -------
__global__ __launch_bounds__(256, 2)
void gemm_kernel() {
    extern __shared__ __align__(16) __nv_bfloat16 dsm[];  // [STG][A | B]
    __shared__ float tailv[TMm + TNn];    // 192
    __shared__ __nv_bfloat16 dummy_sync;  // (unused)

    int tile = blockIdx.x;                // 0..7: mt=tile>>2, nt=tile&3
    int pair = blockIdx.y;
    int slab = blockIdx.z;
    int lt   = pair * 8 + tile;           // logical tile 0..47
    int tm   = (tile >> 2) * TMm;
    int tn   = (tile & 3) * TNn;
    int pi = c_pi[pair], pj = c_pj[pair];
    int kbase = c_kbase[slab], kcnt = c_kcnt[slab];
    const __nv_bfloat16* A = g_z + (size_t)pi * Bn * Dn + (size_t)kbase * KC * Dn + tm;
    const __nv_bfloat16* B = g_z + (size_t)pj * Bn * Dn + (size_t)kbase * KC * Dn + tn;

    int t    = threadIdx.x;               // 256 threads, 8 warps
    int lane = t & 31;
    int w    = t >> 5;
    int wm   = (w >> 1) * 32;             // 4 warp-groups in M (128)
    int wn   = (w & 1) * 32;              // 2 warp-groups in N (64)

    int grp = lane >> 3, r = lane & 7;
    int aRow = ((grp & 2) ? 8 : 0) + r;
    int aCol = wm + ((grp & 1) ? 8 : 0);
    int bRow = ((grp & 1) ? 8 : 0) + r;
    int bOff = ((grp & 2) ? 8 : 0);

    float acc[2][4][4] = {};              // 32 acc regs: 32(M) x 32(N)

    // loader: A = 512 granules (32 rows x 16 segs), B = 256 (32 rows x 8 segs)
    // 768 granules / 256 threads = 3 per thread, 12KB per chunk
    auto issue = [&](int c) {
        if (c < kcnt) {
            __nv_bfloat16* sA = dsm + (size_t)(c & 3) * STAGEE;
            __nv_bfloat16* sB = sA + AOP;
#pragma unroll
            for (int i = 0; i < 3; i++) {
                int g = i * 256 + t;
                if (g < 512) {
                    int row = g >> 4, seg = g & 15;
                    cpa16(&sA[row * ASPAD + seg * 8],
                          A + (size_t)(c * KC + row) * Dn + seg * 8);
                } else {
                    int gb = g - 512;
                    int row = gb >> 3, seg = gb & 7;
                    cpa16(&sB[row * BSPAD + seg * 8],
                          B + (size_t)(c * KC + row) * Dn + seg * 8);
                }
            }
        }
        cp_commit();
    };

    issue(0); issue(1); issue(2);

    // slab 0 prologue: rank-1 tail values
    if (slab == 0) {
        if (t < TMm) {
            float s = 0.0f;
#pragma unroll 16
            for (int c = 0; c < NCHC; c++) s += g_partMean[(pi * NCHC + c) * Dn + tm + t];
            tailv[t] = -64.0f * (s * (1.0f / (float)Bn));
        } else if (t < TMm + TNn) {
            int tt = t - TMm;
            float s = 0.0f;
#pragma unroll 16
            for (int c = 0; c < NCHC; c++) s += g_partMean[(pj * NCHC + c) * Dn + tn + tt];
            tailv[TMm + tt] = 64.0f * (s * (1.0f / (float)Bn));
        }
    }

    for (int c = 0; c < kcnt; ++c) {
        cp_wait2();
        __syncthreads();
        issue(c + 3);

        const __nv_bfloat16* sA = dsm + (size_t)(c & 3) * STAGEE;
        const __nv_bfloat16* sB = sA + AOP;
#pragma unroll
        for (int s = 0; s < 2; ++s) {
            int k0 = s * 16;
            unsigned A0[4], A1[4], Bf[2][4];
            ldm_x4t(A0, &sA[(k0 + aRow) * ASPAD + aCol]);
            ldm_x4t(A1, &sA[(k0 + aRow) * ASPAD + aCol + 16]);
#pragma unroll
            for (int j = 0; j < 2; j++)
                ldm_x4t(Bf[j], &sB[(k0 + bRow) * BSPAD + wn + j * 16 + bOff]);
#pragma unroll
            for (int j = 0; j < 2; j++) {
                mma16816(acc[0][2 * j],     A0, Bf[j][0], Bf[j][1]);
                mma16816(acc[0][2 * j + 1], A0, Bf[j][2], Bf[j][3]);
                mma16816(acc[1][2 * j],     A1, Bf[j][0], Bf[j][1]);
                mma16816(acc[1][2 * j + 1], A1, Bf[j][2], Bf[j][3]);
            }
        }
    }

    // rank-1 tail as one k=16 mma (slab 0 only)
    if (slab == 0) {
        cp_wait0();
        __syncthreads();
        {
            __nv_bfloat16* sA = dsm;
            __nv_bfloat16* sB = dsm + AOP;
            // A tail: 16 rows x 16 segs = 256 granules (one pass, 256 thr)
            {
                int row = t >> 4, seg = t & 15;
                uint4 gA = make_uint4(0u, 0u, 0u, 0u);
                if (row == 0) {
                    unsigned* pa = (unsigned*)&gA;
#pragma unroll
                    for (int q = 0; q < 4; q++) {
                        __nv_bfloat162 va = __floats2bfloat162_rn(
                            tailv[seg * 8 + 2 * q], tailv[seg * 8 + 2 * q + 1]);
                        pa[q] = *(unsigned*)&va;
                    }
                }
                *(uint4*)&sA[row * ASPAD + seg * 8] = gA;
            }
            // B tail: 16 rows x 8 segs = 128 granules (threads 0..127)
            if (t < 128) {
                int row = t >> 3, seg = t & 7;
                uint4 gB = make_uint4(0u, 0u, 0u, 0u);
                if (row == 0) {
                    unsigned* pb = (unsigned*)&gB;
#pragma unroll
                    for (int q = 0; q < 4; q++) {
                        __nv_bfloat162 vb = __floats2bfloat162_rn(
                            tailv[TMm + seg * 8 + 2 * q],
                            tailv[TMm + seg * 8 + 2 * q + 1]);
                        pb[q] = *(unsigned*)&vb;
                    }
                }
                *(uint4*)&sB[row * BSPAD + seg * 8] = gB;
            }
        }
        __syncthreads();
        {
            const __nv_bfloat16* sA = dsm;
            const __nv_bfloat16* sB = dsm + AOP;
            unsigned A0[4], A1[4], Bf[2][4];
            ldm_x4t(A0, &sA[aRow * ASPAD + aCol]);
            ldm_x4t(A1, &sA[aRow * ASPAD + aCol + 16]);
#pragma unroll
            for (int j = 0; j < 2; j++)
                ldm_x4t(Bf[j], &sB[bRow * BSPAD + wn + j * 16 + bOff]);
#pragma unroll
            for (int j = 0; j < 2; j++) {
                mma16816(acc[0][2 * j],     A0, Bf[j][0], Bf[j][1]);
                mma16816(acc[0][2 * j + 1], A0, Bf[j][2], Bf[j][3]);
                mma16816(acc[1][2 * j],     A1, Bf[j][0], Bf[j][1]);
                mma16816(acc[1][2 * j + 1], A1, Bf[j][2], Bf[j][3]);
            }
        }
    }

    // store partial fragments (layout-oblivious, same bijection all slabs)
    {
        float4* dst4 = (float4*)(g_partC + (size_t)slab * CSTRIDE + (size_t)lt * TILEF);
#pragma unroll
        for (int mi = 0; mi < 2; mi++)
#pragma unroll
            for (int nj = 0; nj < 4; nj++)
                dst4[(mi * 4 + nj) * 256 + t] = make_float4(
                    acc[mi][nj][0], acc[mi][nj][1], acc[mi][nj][2], acc[mi][nj][3]);
    }
}

// -------- kernel 3: combine 6 slabs (float4), square, fused final ---------
__global__ void sq_kernel(float* __restrict__ out) {
    __shared__ float red[256];
    __shared__ int s_last;
    int t = threadIdx.x;
    const float4* pc = (const float4*)g_partC;
    const int S4 = CSTRIDE / 4;
    int idx0 = blockIdx.x * 512 + t;
    float s = 0.0f;
#pragma unroll
    for (int u = 0; u < 2; u++) {
        int idx = idx0 + u * 256;
        float vx = 0.f, vy = 0.f, vz = 0.f, vw = 0.f;
#pragma unroll
        for (int s2 = 0; s2 < SPLITK; s2++) {
            float4 v = pc[s2 * S4 + idx];
            vx += v.x; vy += v.y; vz += v.z; vw += v.w;
        }
        s += vx * vx + vy * vy + vz * vz + vw * vw;
    }
#pragma unroll
    for (int o = 16; o > 0; o >>= 1) s += __shfl_xor_sync(0xffffffffu, s, o);
    if ((t & 31) == 0) red[t >> 5] = s;
    __syncthreads();
    if (t == 0) {
        float tot = 0.0f;
#pragma unroll
        for (int i = 0; i < 8; ++i) tot += red[i];
        g_bsum[blockIdx.x] = tot;
        __threadfence();
        unsigned tk = atomicAdd(&g_cnt, 1u);
        s_last = (tk == SQBLK - 1) ? 1 : 0;
    }
    __syncthreads();

    if (s_last) {
        __threadfence();
        red[t] = (t < SQBLK) ? g_bsum[t] : 0.0f;
        __syncthreads();
#pragma unroll
        for (int o = 128; o > 0; o >>= 1) {
            if (t < o) red[t] += red[t + o];
            __syncthreads();
        }
        if (t == 0) {
            const float denom = 4095.0f * 4095.0f;
            out[0] = 0.1f * (red[0] / denom) * (1.0f / (float)NPAIR);
        }
    }
}

// -------- launch ----------------------------------------------------------
extern "C" void kernel_launch(void* const* d_in, const int* in_sizes, int n_in,
                              void* d_out, int out_size) {
    const float* e0 = (const float*)d_in[0];
    const float* e1 = (const float*)d_in[1];
    const float* e2 = (const float*)d_in[2];
    const float* e3 = (const float*)d_in[3];
    float* out = (float*)d_out;

    cudaFuncSetAttribute(gemm_kernel,
                         cudaFuncAttributeMaxDynamicSharedMemorySize, DYN_SMEM);

    conv_colsum_kernel<<<dim3(NCHC, NEXP), 256>>>(e0, e1, e2, e3);
    gemm_kernel<<<dim3(8, NPAIR, SPLITK), 256, DYN_SMEM>>>();
    sq_kernel<<<SQBLK, 256>>>(out);
}